// round 1
// baseline (speedup 1.0000x reference)
#include <cuda_runtime.h>
#include <math.h>

#define TOKENS 16384
#define Dm 2048
#define Em 128
#define Hm 128
#define MT 64          // tokens per CTA
#define KC 32          // k-chunk
#define NCHUNK (Dm / KC)
#define XS_STRIDE 36   // padded row stride for xs (16B aligned, conflict-free)
#define WDT_STRIDE 132 // padded row stride for decoder weight in smem

// Pre-transposed weights (device scratch; no dynamic allocation allowed)
__device__ float g_WrT[Dm * Em];  // [k][e]
__device__ float g_WdT[Em * Hm];  // [e][h]

__device__ __forceinline__ unsigned long long pk2(float x, float y) {
    unsigned long long r;
    asm("mov.b64 %0, {%1, %2};" : "=l"(r) : "f"(x), "f"(y));
    return r;
}
__device__ __forceinline__ void fma2(unsigned long long& d, unsigned long long a, unsigned long long b) {
    asm("fma.rn.f32x2 %0, %1, %2, %0;" : "+l"(d) : "l"(a), "l"(b));
}
__device__ __forceinline__ float2 up2(unsigned long long v) {
    float2 r;
    asm("mov.b64 {%0, %1}, %2;" : "=f"(r.x), "=f"(r.y) : "l"(v));
    return r;
}

// Generic 32x32 tiled transpose: in[R][C] -> out[C][R]
__global__ void tr_kernel(const float* __restrict__ in, float* __restrict__ out, int R, int C) {
    __shared__ float tile[32][33];
    int x = blockIdx.x * 32 + threadIdx.x;
#pragma unroll
    for (int j = 0; j < 32; j += 8) {
        int y = blockIdx.y * 32 + threadIdx.y + j;
        if (y < R && x < C) tile[threadIdx.y + j][threadIdx.x] = in[(size_t)y * C + x];
    }
    __syncthreads();
    int x2 = blockIdx.y * 32 + threadIdx.x;
#pragma unroll
    for (int j = 0; j < 32; j += 8) {
        int y2 = blockIdx.x * 32 + threadIdx.y + j;
        if (y2 < C && x2 < R) out[(size_t)y2 * R + x2] = tile[threadIdx.x][threadIdx.y + j];
    }
}

struct SmemLayout {
    union {
        struct {
            float xs[MT * XS_STRIDE];   // 9216 B
            float ws[KC * Em];          // 16384 B
        } g;
        float emb[MT * Em];             // 32768 B
    } u;
    float wdt[Em * WDT_STRIDE];         // 67584 B
    float gbuf[8 * Hm];                 // 4096 B
    float abuf[8 * Hm];                 // 4096 B
    float rnn[Em];
    float gam[Em];
    float bet[Em];
};

__global__ __launch_bounds__(256) void fused_kernel(
    const float* __restrict__ x,
    const float* __restrict__ gumbel,
    const float* __restrict__ rnn_g,
    const float* __restrict__ gamma_g,
    const float* __restrict__ beta_g,
    const int* __restrict__ topk_p,
    float* __restrict__ out_bin,
    float* __restrict__ out_ap)
{
    extern __shared__ char smraw[];
    SmemLayout* sm = reinterpret_cast<SmemLayout*>(smraw);
    const int tid = threadIdx.x;
    const int t0 = blockIdx.x * MT;

    // ---- stage decoder weight + LN params into smem ----
#pragma unroll
    for (int p = 0; p < 16; p++) {
        int n = tid + 256 * p;
        int e = n >> 5;
        int h4 = (n & 31) * 4;
        *(float4*)&sm->wdt[e * WDT_STRIDE + h4] = *(const float4*)&g_WdT[e * Hm + h4];
    }
    if (tid < 128) {
        sm->rnn[tid] = rnn_g[tid];
        sm->gam[tid] = gamma_g[tid];
        sm->bet[tid] = beta_g[tid];
    }

    // ---- GEMM1: acc[r][e] = sum_k x[t0+r][k] * Wr[e][k] ----
    const int c0 = tid & 15;  // col group: cols c0*8 .. c0*8+7
    const int rg = tid >> 4;  // row group: rows rg*4 .. rg*4+3
    const int r0 = rg * 4;

    unsigned long long acc[4][4];
#pragma unroll
    for (int i = 0; i < 4; i++)
#pragma unroll
        for (int j = 0; j < 4; j++) acc[i][j] = 0ull;

    // global-load mappings (prefetch into regs, then STS.128)
    const int xr = tid >> 3;          // 0..31 (two passes: +0, +32)
    const int xc4 = (tid & 7) * 4;    // k offset within chunk
    const int wc4 = (tid & 31) * 4;   // e offset

    float4 xf[2], wf[4];
    {
        const float* xg = x + (size_t)t0 * Dm;
#pragma unroll
        for (int p = 0; p < 2; p++)
            xf[p] = *(const float4*)&xg[(size_t)(xr + 32 * p) * Dm + xc4];
#pragma unroll
        for (int p = 0; p < 4; p++) {
            int wk = (tid + 256 * p) >> 5;
            wf[p] = *(const float4*)&g_WrT[wk * Em + wc4];
        }
    }

    for (int ch = 0; ch < NCHUNK; ++ch) {
        __syncthreads();
#pragma unroll
        for (int p = 0; p < 2; p++)
            *(float4*)&sm->u.g.xs[(xr + 32 * p) * XS_STRIDE + xc4] = xf[p];
#pragma unroll
        for (int p = 0; p < 4; p++) {
            int wk = (tid + 256 * p) >> 5;
            *(float4*)&sm->u.g.ws[wk * Em + wc4] = wf[p];
        }
        __syncthreads();

        if (ch + 1 < NCHUNK) {
            const int k0 = (ch + 1) * KC;
            const float* xg = x + (size_t)t0 * Dm + k0;
#pragma unroll
            for (int p = 0; p < 2; p++)
                xf[p] = *(const float4*)&xg[(size_t)(xr + 32 * p) * Dm + xc4];
#pragma unroll
            for (int p = 0; p < 4; p++) {
                int wk = (tid + 256 * p) >> 5;
                wf[p] = *(const float4*)&g_WrT[(k0 + wk) * Em + wc4];
            }
        }

#pragma unroll
        for (int kk = 0; kk < KC; kk += 4) {
            float4 xv[4];
#pragma unroll
            for (int i = 0; i < 4; i++)
                xv[i] = *(const float4*)&sm->u.g.xs[(r0 + i) * XS_STRIDE + kk];
#pragma unroll
            for (int q = 0; q < 4; q++) {
                ulonglong2 w01 = *(const ulonglong2*)&sm->u.g.ws[(kk + q) * Em + c0 * 8];
                ulonglong2 w23 = *(const ulonglong2*)&sm->u.g.ws[(kk + q) * Em + c0 * 8 + 4];
#pragma unroll
                for (int i = 0; i < 4; i++) {
                    float a = (q == 0) ? xv[i].x : (q == 1) ? xv[i].y : (q == 2) ? xv[i].z : xv[i].w;
                    unsigned long long a2 = pk2(a, a);
                    fma2(acc[i][0], a2, w01.x);
                    fma2(acc[i][1], a2, w01.y);
                    fma2(acc[i][2], a2, w23.x);
                    fma2(acc[i][3], a2, w23.y);
                }
            }
        }
    }

    __syncthreads();  // done reading xs/ws; emb aliases them
#pragma unroll
    for (int i = 0; i < 4; i++)
#pragma unroll
        for (int j = 0; j < 4; j++) {
            float2 v = up2(acc[i][j]);
            *(float2*)&sm->u.emb[(r0 + i) * Em + c0 * 8 + j * 2] = v;
        }
    __syncthreads();

    // ---- Phase 2: per-token LN -> GELU -> decoder -> gumbel-sigmoid -> mask ----
    const int w = tid >> 5;
    const int lane = tid & 31;
    const int K = *topk_p;
    const float Kf = (float)K;

    for (int tt = 0; tt < 8; ++tt) {
        const int t = w * 8 + tt;
        const int gt = t0 + t;

        float v[4];
#pragma unroll
        for (int j = 0; j < 4; j++) {
            int e = lane + 32 * j;
            v[j] = sm->u.emb[t * Em + e] + sm->rnn[e];
        }
        float s = v[0] + v[1] + v[2] + v[3];
#pragma unroll
        for (int o = 16; o > 0; o >>= 1) s += __shfl_xor_sync(0xffffffffu, s, o);
        const float mu = s * (1.0f / 128.0f);
        float q = 0.f;
#pragma unroll
        for (int j = 0; j < 4; j++) { float d = v[j] - mu; q += d * d; }
#pragma unroll
        for (int o = 16; o > 0; o >>= 1) q += __shfl_xor_sync(0xffffffffu, q, o);
        const float inv = rsqrtf(q * (1.0f / 128.0f) + 1e-5f);

        __syncwarp();  // gbuf reuse fence (previous token's reads done)
#pragma unroll
        for (int j = 0; j < 4; j++) {
            int e = lane + 32 * j;
            float h = (v[j] - mu) * inv * sm->gam[e] + sm->bet[e];
            sm->gbuf[w * Hm + e] = 0.5f * h * (1.0f + erff(h * 0.70710678118654752f));
        }
        __syncwarp();

        // decoder: logits[h] = sum_e g[e] * Wd[h][e], h = lane*4 + jj
        unsigned long long l0 = 0ull, l1 = 0ull;
#pragma unroll 4
        for (int e = 0; e < Em; e++) {
            float a = sm->gbuf[w * Hm + e];
            unsigned long long a2 = pk2(a, a);
            ulonglong2 wd = *(const ulonglong2*)&sm->wdt[e * WDT_STRIDE + lane * 4];
            fma2(l0, a2, wd.x);
            fma2(l1, a2, wd.y);
        }
        float2 p0 = up2(l0), p1 = up2(l1);
        float lg[4] = {p0.x, p0.y, p1.x, p1.y};

        float4 gu = *(const float4*)&gumbel[(size_t)gt * Hm + lane * 4];
        float gua[4] = {gu.x, gu.y, gu.z, gu.w};

        float ap[4], bn[4];
        float csum = 0.f;
#pragma unroll
        for (int jj = 0; jj < 4; jj++) {
            float z = (lg[jj] + gua[jj] + 3.0f) * 2.5f;   // /0.4
            ap[jj] = 1.0f / (1.0f + expf(-z));
            bn[jj] = rintf(ap[jj]);                       // round-half-even, matches jnp.round
            csum += bn[jj];
        }
#pragma unroll
        for (int o = 16; o > 0; o >>= 1) csum += __shfl_xor_sync(0xffffffffu, csum, o);

        float ob[4];
        if (csum > Kf || csum == 0.0f) {      // warp-uniform branch
            const int kneed = (csum > Kf) ? K : 1;  // top-k mask or argmax fallback
#pragma unroll
            for (int jj = 0; jj < 4; jj++) sm->abuf[w * Hm + lane * 4 + jj] = ap[jj];
            __syncwarp();
            int r[4] = {0, 0, 0, 0};
            for (int j4 = 0; j4 < Hm; j4 += 4) {
                float4 av = *(const float4*)&sm->abuf[w * Hm + j4];
                float aj[4] = {av.x, av.y, av.z, av.w};
#pragma unroll
                for (int u = 0; u < 4; u++) {
                    int j = j4 + u;
#pragma unroll
                    for (int jj = 0; jj < 4; jj++) {
                        int idx = lane * 4 + jj;
                        // stable rank: (value desc, index asc) — matches lax.top_k / argmax
                        r[jj] += (aj[u] > ap[jj]) || (aj[u] == ap[jj] && j < idx);
                    }
                }
            }
#pragma unroll
            for (int jj = 0; jj < 4; jj++) ob[jj] = (r[jj] < kneed) ? 1.0f : 0.0f;
            __syncwarp();  // abuf reuse fence
        } else {
#pragma unroll
            for (int jj = 0; jj < 4; jj++) ob[jj] = bn[jj];
        }

        *(float4*)&out_bin[(size_t)gt * Hm + lane * 4] = make_float4(ob[0], ob[1], ob[2], ob[3]);
        if (out_ap)
            *(float4*)&out_ap[(size_t)gt * Hm + lane * 4] = make_float4(ap[0], ap[1], ap[2], ap[3]);
    }
}

extern "C" void kernel_launch(void* const* d_in, const int* in_sizes, int n_in,
                              void* d_out, int out_size) {
    const float* x        = (const float*)d_in[0];  // [B,S,D]
    const float* W_router = (const float*)d_in[1];  // [E,D]
    const float* W_dec    = (const float*)d_in[2];  // [H,E]
    const float* ln_gamma = (const float*)d_in[3];  // [E]
    const float* ln_beta  = (const float*)d_in[4];  // [E]
    const float* rnn      = (const float*)d_in[5];  // [E]
    const float* gumbel   = (const float*)d_in[6];  // [B,S,H]
    const int*   topk     = (const int*)d_in[7];    // scalar

    float* out_bin = (float*)d_out;
    const size_t N = (size_t)TOKENS * Hm;
    float* out_ap = ((size_t)out_size >= 2 * N) ? out_bin + N : nullptr;

    float *wrt_ptr = nullptr, *wdt_ptr = nullptr;
    cudaGetSymbolAddress((void**)&wrt_ptr, g_WrT);
    cudaGetSymbolAddress((void**)&wdt_ptr, g_WdT);

    // Pre-transpose weights so GEMM smem fills are coalesced + conflict-free.
    tr_kernel<<<dim3(Dm / 32, Em / 32), dim3(32, 8)>>>(W_router, wrt_ptr, Em, Dm);
    tr_kernel<<<dim3(Em / 32, Hm / 32), dim3(32, 8)>>>(W_dec, wdt_ptr, Hm, Em);

    const int smem_bytes = (int)sizeof(SmemLayout);
    cudaFuncSetAttribute(fused_kernel, cudaFuncAttributeMaxDynamicSharedMemorySize, smem_bytes);

    fused_kernel<<<TOKENS / MT, 256, smem_bytes>>>(
        x, gumbel, rnn, ln_gamma, ln_beta, topk, out_bin, out_ap);
}